// round 7
// baseline (speedup 1.0000x reference)
#include <cuda_runtime.h>
#include <float.h>

#define NOFF    44
#define NDENSE  33
#define NSPARSE 11
#define HD      64
#define SEQ     8192
#define HNUM    16
#define BNUM    2
#define TPB     128
#define NWARP   (TPB / 32)
#define QT      4                  // queries per octet
#define QPW     (4 * QT)           // 16 queries per warp
#define QPB     (NWARP * QPW)      // 64 queries per block
#define SPAD    45                 // padded score row (kills bank conflicts)

typedef unsigned long long ull;

__constant__ int c_soff[NSPARSE] = {48,64,96,128,192,256,384,512,768,1024,1536};

// ---- packed f32x2 helpers (Blackwell FFMA2 path, PTX-only) ----
__device__ __forceinline__ ull f2fma(ull a, ull b, ull c) {
    ull d; asm("fma.rn.f32x2 %0, %1, %2, %3;" : "=l"(d) : "l"(a), "l"(b), "l"(c)); return d;
}
__device__ __forceinline__ ull f2add(ull a, ull b) {
    ull d; asm("add.rn.f32x2 %0, %1, %2;" : "=l"(d) : "l"(a), "l"(b)); return d;
}
__device__ __forceinline__ ull f2mul(ull a, ull b) {
    ull d; asm("mul.rn.f32x2 %0, %1, %2;" : "=l"(d) : "l"(a), "l"(b)); return d;
}
__device__ __forceinline__ ull f2pack(float lo, float hi) {
    ull d; asm("mov.b64 %0, {%1, %2};" : "=l"(d) : "f"(lo), "f"(hi)); return d;
}
__device__ __forceinline__ float2 f2unpack(ull v) {
    float lo, hi; asm("mov.b64 {%0, %1}, %2;" : "=f"(lo), "=f"(hi) : "l"(v));
    return make_float2(lo, hi);
}

__device__ __forceinline__ float dot8p(ulonglong2 qa, ulonglong2 qb,
                                       ulonglong2 b0, ulonglong2 b1) {
    ull acc = f2mul(qa.x, b0.x);
    acc = f2fma(qa.y, b0.y, acc);
    acc = f2fma(qb.x, b1.x, acc);
    acc = f2fma(qb.y, b1.y, acc);
    float2 r = f2unpack(acc);
    return r.x + r.y;
}

__device__ __forceinline__ ulonglong2 u2add(ulonglong2 a, ulonglong2 b) {
    ulonglong2 r; r.x = f2add(a.x, b.x); r.y = f2add(a.y, b.y); return r;
}

__device__ __forceinline__ float red8(float p) {
    p += __shfl_xor_sync(0xffffffffu, p, 1);
    p += __shfl_xor_sync(0xffffffffu, p, 2);
    p += __shfl_xor_sync(0xffffffffu, p, 4);
    return p;
}

__global__ __launch_bounds__(TPB, 5)
void dsqg_attn_kernel(const float* __restrict__ q,
                      const float* __restrict__ k,
                      const float* __restrict__ v,
                      const float* __restrict__ pb,
                      const float* __restrict__ se,
                      const float* __restrict__ ph,
                      float* __restrict__ out) {
    const int lane = threadIdx.x & 31;
    const int wid  = threadIdx.x >> 5;
    const int o    = lane >> 3;      // octet id (0..3)
    const int ln8  = lane & 7;       // lane within octet

    __shared__ ulonglong2 s_se[NOFF * 16];
    __shared__ float  s_pb[NOFF];
    __shared__ float  s_cos[NOFF];
    __shared__ float  s_sin[NOFF];
    __shared__ float  s_p[QPB][SPAD];

    for (int i = threadIdx.x; i < NOFF * 16; i += TPB)
        s_se[i] = ((const ulonglong2*)se)[i];
    if (threadIdx.x < NOFF) {
        const int h0 = blockIdx.y;
        s_pb[threadIdx.x] = pb[threadIdx.x * HNUM + h0];
        float p = ph[threadIdx.x * HNUM + h0];
        s_cos[threadIdx.x] = cosf(p);
        s_sin[threadIdx.x] = sinf(p);
    }
    __syncthreads();

    const int h = blockIdx.y;
    const int b = blockIdx.z;
    const size_t bh = ((size_t)b * HNUM + h) * SEQ;
    const ulonglong2* kb = (const ulonglong2*)(k + bh * HD);
    const ulonglong2* vb = (const ulonglong2*)(v + bh * HD);

    const int ql0 = wid * QPW + o * QT;
    const int n0  = blockIdx.x * QPB + ql0;
    const int n3  = n0 + 3;

    const float sc = 0.125f;   // 1/sqrt(64)

    // ================= pass 1: dense scores (4-deep row FIFO, packed) =================
    {
        ulonglong2 qa[QT], qbr[QT];
        #pragma unroll
        for (int t = 0; t < QT; t++) {
            const ulonglong2* qp = (const ulonglong2*)(q + (bh + (size_t)(n0 + t)) * HD);
            qa[t]  = qp[ln8];
            qbr[t] = qp[8 + ln8];
        }

        ulonglong2 f0[4], f1[4];
        #pragma unroll
        for (int j = 0; j < 4; j++) {
            const ulonglong2* kr = kb + (size_t)(n3 - j) * 16;
            f0[j] = kr[ln8];
            f1[j] = kr[8 + ln8];
        }
        #pragma unroll 3
        for (int d = 0; d < NDENSE; d++) {
            ulonglong2 e0 = s_se[d * 16 + ln8];
            ulonglong2 e1 = s_se[d * 16 + 8 + ln8];
            float p3 = dot8p(qa[3], qbr[3], u2add(f0[0], e0), u2add(f1[0], e1));
            float p2 = dot8p(qa[2], qbr[2], u2add(f0[1], e0), u2add(f1[1], e1));
            float p1 = dot8p(qa[1], qbr[1], u2add(f0[2], e0), u2add(f1[2], e1));
            float p0 = dot8p(qa[0], qbr[0], u2add(f0[3], e0), u2add(f1[3], e1));
            int rn = n0 - d - 1;
            int rc = rn < 0 ? 0 : rn;
            f0[0] = f0[1]; f1[0] = f1[1];
            f0[1] = f0[2]; f1[1] = f1[2];
            f0[2] = f0[3]; f1[2] = f1[3];
            {
                const ulonglong2* kr = kb + (size_t)rc * 16;
                f0[3] = kr[ln8];
                f1[3] = kr[8 + ln8];
            }
            p3 = red8(p3); p2 = red8(p2); p1 = red8(p1); p0 = red8(p0);
            if (ln8 == 0) {
                float bias = s_pb[d];
                s_p[ql0 + 3][d] = (n3     >= d) ? fmaf(p3, sc, bias) : -1e30f;
                s_p[ql0 + 2][d] = (n0 + 2 >= d) ? fmaf(p2, sc, bias) : -1e30f;
                s_p[ql0 + 1][d] = (n0 + 1 >= d) ? fmaf(p1, sc, bias) : -1e30f;
                s_p[ql0    ][d] = (n0     >= d) ? fmaf(p0, sc, bias) : -1e30f;
            }
        }

        // ---- sparse scores ----
        #pragma unroll
        for (int i = 0; i < NSPARSE; i++) {
            const int d  = c_soff[i];
            const int io = NDENSE + i;
            ulonglong2 e0 = s_se[io * 16 + ln8];
            ulonglong2 e1 = s_se[io * 16 + 8 + ln8];
            float ps_[QT];
            #pragma unroll
            for (int t = 0; t < QT; t++) {
                int r  = n0 + t - d;
                int rc = r < 0 ? 0 : r;
                const ulonglong2* kr = kb + (size_t)rc * 16;
                ps_[t] = dot8p(qa[t], qbr[t], u2add(kr[ln8], e0), u2add(kr[8 + ln8], e1));
            }
            #pragma unroll
            for (int t = 0; t < QT; t++) ps_[t] = red8(ps_[t]);
            if (ln8 == 0) {
                float bias = s_pb[io];
                #pragma unroll
                for (int t = 0; t < QT; t++)
                    s_p[ql0 + t][io] = (n0 + t >= d) ? fmaf(ps_[t], sc, bias) : -1e30f;
            }
        }
    }
    __syncwarp();

    // ====== softmax: 2 lanes per query, 22 offsets each ======
    {
        const int qloc = wid * QPW + (lane & 15);
        const int half = lane >> 4;
        const int base = half * 22;
        float vals[22];
        float vmax = -FLT_MAX;
        #pragma unroll
        for (int t = 0; t < 22; t++) {
            vals[t] = s_p[qloc][base + t];
            vmax = fmaxf(vmax, vals[t]);
        }
        vmax = fmaxf(vmax, __shfl_xor_sync(0xffffffffu, vmax, 16));
        float sum = 0.f;
        #pragma unroll
        for (int t = 0; t < 22; t++) {
            vals[t] = __expf(vals[t] - vmax);
            sum += vals[t];
        }
        sum += __shfl_xor_sync(0xffffffffu, sum, 16);
        const float inv = 1.0f / sum;
        #pragma unroll
        for (int t = 0; t < 22; t++)
            s_p[qloc][base + t] = vals[t] * inv;
    }
    __syncwarp();

    // ========== pass 2: A = sum(w*c*v), B = sum(w*s*v), rotate at end ==========
    ulonglong2 A0[QT], A1[QT], B0[QT], B1[QT];
    #pragma unroll
    for (int t = 0; t < QT; t++) {
        A0[t].x = A0[t].y = A1[t].x = A1[t].y = 0ull;
        B0[t].x = B0[t].y = B1[t].x = B1[t].y = 0ull;
    }

    // dense: ROW iteration, single live row (no FIFO).
    // row r = n3 - j contributes to query n0+t at offset idx = j + t - 3.
    // p == 0 exactly when (t, idx) is invalid/causally masked, so weights self-mask.
    #pragma unroll 4
    for (int j = 0; j < NDENSE + 3; j++) {       // 36 iterations
        int r  = n3 - j;
        int rc = r < 0 ? 0 : r;
        const ulonglong2* vr = vb + (size_t)rc * 16;
        ulonglong2 v0 = vr[ln8];
        ulonglong2 v1 = vr[8 + ln8];
        #pragma unroll
        for (int t = 0; t < QT; t++) {
            int idx = j + t - 3;
            int ic  = idx < 0 ? 0 : (idx > 32 ? 32 : idx);
            bool ok = (idx >= 0) && (idx <= 32);
            float w = ok ? s_p[ql0 + t][ic] : 0.f;
            float cc = s_cos[ic], ss = s_sin[ic];
            float wc = w * cc, ws = w * ss;
            ull pcp = f2pack(wc, wc);
            ull psp = f2pack(ws, ws);
            A0[t].x = f2fma(v0.x, pcp, A0[t].x);
            A0[t].y = f2fma(v0.y, pcp, A0[t].y);
            A1[t].x = f2fma(v1.x, pcp, A1[t].x);
            A1[t].y = f2fma(v1.y, pcp, A1[t].y);
            B0[t].x = f2fma(v0.x, psp, B0[t].x);
            B0[t].y = f2fma(v0.y, psp, B0[t].y);
            B1[t].x = f2fma(v1.x, psp, B1[t].x);
            B1[t].y = f2fma(v1.y, psp, B1[t].y);
        }
    }

    // sparse (distinct rows per query; p == 0 self-masks)
    #pragma unroll
    for (int i = 0; i < NSPARSE; i++) {
        const int d  = c_soff[i];
        const int io = NDENSE + i;
        float cc = s_cos[io], ss = s_sin[io];
        #pragma unroll
        for (int t = 0; t < QT; t++) {
            int r  = n0 + t - d;
            int rc = r < 0 ? 0 : r;
            float w  = s_p[ql0 + t][io];
            float wc = w * cc, ws = w * ss;
            ull pcp = f2pack(wc, wc);
            ull psp = f2pack(ws, ws);
            const ulonglong2* vr = vb + (size_t)rc * 16;
            ulonglong2 v0 = vr[ln8];
            ulonglong2 v1 = vr[8 + ln8];
            A0[t].x = f2fma(v0.x, pcp, A0[t].x);
            A0[t].y = f2fma(v0.y, pcp, A0[t].y);
            A1[t].x = f2fma(v1.x, pcp, A1[t].x);
            A1[t].y = f2fma(v1.y, pcp, A1[t].y);
            B0[t].x = f2fma(v0.x, psp, B0[t].x);
            B0[t].y = f2fma(v0.y, psp, B0[t].y);
            B1[t].x = f2fma(v1.x, psp, B1[t].x);
            B1[t].y = f2fma(v1.y, psp, B1[t].y);
        }
    }

    // ================= final rotation + store =================
    #pragma unroll
    for (int t = 0; t < QT; t++) {
        float4* op = (float4*)(out + (bh + (size_t)(n0 + t)) * HD);
        float2 a0 = f2unpack(A0[t].x), b0 = f2unpack(B0[t].x);
        float2 a1 = f2unpack(A0[t].y), b1 = f2unpack(B0[t].y);
        float2 a2 = f2unpack(A1[t].x), b2 = f2unpack(B1[t].x);
        float2 a3 = f2unpack(A1[t].y), b3 = f2unpack(B1[t].y);
        float4 r0, r1;
        r0.x = a0.x - b0.y;  r0.y = a0.y + b0.x;
        r0.z = a1.x - b1.y;  r0.w = a1.y + b1.x;
        r1.x = a2.x - b2.y;  r1.y = a2.y + b2.x;
        r1.z = a3.x - b3.y;  r1.w = a3.y + b3.x;
        op[ln8]     = r0;
        op[8 + ln8] = r1;
    }
}

extern "C" void kernel_launch(void* const* d_in, const int* in_sizes, int n_in,
                              void* d_out, int out_size) {
    const float* q  = (const float*)d_in[0];
    const float* k  = (const float*)d_in[1];
    const float* v  = (const float*)d_in[2];
    const float* pb = (const float*)d_in[3];
    const float* se = (const float*)d_in[4];
    const float* ph = (const float*)d_in[5];
    float* out = (float*)d_out;

    dim3 grid(SEQ / QPB, HNUM, BNUM);
    dsqg_attn_kernel<<<grid, TPB>>>(q, k, v, pb, se, ph, out);
}

// round 8
// speedup vs baseline: 1.2673x; 1.2673x over previous
#include <cuda_runtime.h>
#include <float.h>

#define NOFF    44
#define NDENSE  33
#define NSPARSE 11
#define HD      64
#define SEQ     8192
#define HNUM    16
#define BNUM    2
#define TPB     128
#define NWARP   (TPB / 32)
#define QT      4                  // queries per octet
#define QPW     (4 * QT)           // 16 queries per warp
#define QPB     (NWARP * QPW)      // 64 queries per block
#define SPAD    45                 // padded score row (kills bank conflicts)

typedef unsigned long long ull;

// scratch: per (b,h,n) the 44 pre-multiplied weights (w*cos, w*sin)
__device__ float2 g_w[(size_t)BNUM * HNUM * SEQ * NOFF];

__constant__ int c_soff[NSPARSE] = {48,64,96,128,192,256,384,512,768,1024,1536};

// ---- packed f32x2 helpers (Blackwell FFMA2 path, PTX-only) ----
__device__ __forceinline__ ull f2fma(ull a, ull b, ull c) {
    ull d; asm("fma.rn.f32x2 %0, %1, %2, %3;" : "=l"(d) : "l"(a), "l"(b), "l"(c)); return d;
}
__device__ __forceinline__ ull f2add(ull a, ull b) {
    ull d; asm("add.rn.f32x2 %0, %1, %2;" : "=l"(d) : "l"(a), "l"(b)); return d;
}
__device__ __forceinline__ ull f2mul(ull a, ull b) {
    ull d; asm("mul.rn.f32x2 %0, %1, %2;" : "=l"(d) : "l"(a), "l"(b)); return d;
}
__device__ __forceinline__ ull f2pack(float lo, float hi) {
    ull d; asm("mov.b64 %0, {%1, %2};" : "=l"(d) : "f"(lo), "f"(hi)); return d;
}
__device__ __forceinline__ float2 f2unpack(ull v) {
    float lo, hi; asm("mov.b64 {%0, %1}, %2;" : "=f"(lo), "=f"(hi) : "l"(v));
    return make_float2(lo, hi);
}

__device__ __forceinline__ float dot8p(ulonglong2 qa, ulonglong2 qb,
                                       ulonglong2 b0, ulonglong2 b1) {
    ull acc = f2mul(qa.x, b0.x);
    acc = f2fma(qa.y, b0.y, acc);
    acc = f2fma(qb.x, b1.x, acc);
    acc = f2fma(qb.y, b1.y, acc);
    float2 r = f2unpack(acc);
    return r.x + r.y;
}

__device__ __forceinline__ ulonglong2 u2add(ulonglong2 a, ulonglong2 b) {
    ulonglong2 r; r.x = f2add(a.x, b.x); r.y = f2add(a.y, b.y); return r;
}

__device__ __forceinline__ float red8(float p) {
    p += __shfl_xor_sync(0xffffffffu, p, 1);
    p += __shfl_xor_sync(0xffffffffu, p, 2);
    p += __shfl_xor_sync(0xffffffffu, p, 4);
    return p;
}

// =====================================================================
// Kernel A: scores + softmax -> g_w = (w*cos, w*sin)
// =====================================================================
__global__ __launch_bounds__(TPB, 5)
void dsqg_scores_kernel(const float* __restrict__ q,
                        const float* __restrict__ k,
                        const float* __restrict__ pb,
                        const float* __restrict__ se,
                        const float* __restrict__ ph) {
    const int lane = threadIdx.x & 31;
    const int wid  = threadIdx.x >> 5;
    const int o    = lane >> 3;
    const int ln8  = lane & 7;

    __shared__ ulonglong2 s_se[NOFF * 16];
    __shared__ float  s_pb[NOFF];
    __shared__ float  s_cos[NOFF];
    __shared__ float  s_sin[NOFF];
    __shared__ float  s_wc[QPB][SPAD];
    __shared__ float  s_ws[QPB][SPAD];

    for (int i = threadIdx.x; i < NOFF * 16; i += TPB)
        s_se[i] = ((const ulonglong2*)se)[i];
    if (threadIdx.x < NOFF) {
        const int h0 = blockIdx.y;
        s_pb[threadIdx.x] = pb[threadIdx.x * HNUM + h0];
        float p = ph[threadIdx.x * HNUM + h0];
        s_cos[threadIdx.x] = cosf(p);
        s_sin[threadIdx.x] = sinf(p);
    }
    __syncthreads();

    const int h = blockIdx.y;
    const int b = blockIdx.z;
    const size_t bh = ((size_t)b * HNUM + h) * SEQ;
    const ulonglong2* kb = (const ulonglong2*)(k + bh * HD);

    const int ql0 = wid * QPW + o * QT;
    const int nB  = blockIdx.x * QPB;
    const int n0  = nB + ql0;
    const int n3  = n0 + 3;

    const float sc = 0.125f;   // 1/sqrt(64)

    // ---- q registers ----
    ulonglong2 qa[QT], qbr[QT];
    #pragma unroll
    for (int t = 0; t < QT; t++) {
        const ulonglong2* qp = (const ulonglong2*)(q + (bh + (size_t)(n0 + t)) * HD);
        qa[t]  = qp[ln8];
        qbr[t] = qp[8 + ln8];
    }

    // ---- dense scores (4-deep row FIFO, packed) ----
    {
        ulonglong2 f0[4], f1[4];
        #pragma unroll
        for (int j = 0; j < 4; j++) {
            const ulonglong2* kr = kb + (size_t)(n3 - j) * 16;
            f0[j] = kr[ln8];
            f1[j] = kr[8 + ln8];
        }
        #pragma unroll 3
        for (int d = 0; d < NDENSE; d++) {
            ulonglong2 e0 = s_se[d * 16 + ln8];
            ulonglong2 e1 = s_se[d * 16 + 8 + ln8];
            float p3 = dot8p(qa[3], qbr[3], u2add(f0[0], e0), u2add(f1[0], e1));
            float p2 = dot8p(qa[2], qbr[2], u2add(f0[1], e0), u2add(f1[1], e1));
            float p1 = dot8p(qa[1], qbr[1], u2add(f0[2], e0), u2add(f1[2], e1));
            float p0 = dot8p(qa[0], qbr[0], u2add(f0[3], e0), u2add(f1[3], e1));
            int rn = n0 - d - 1;
            int rc = rn < 0 ? 0 : rn;
            f0[0] = f0[1]; f1[0] = f1[1];
            f0[1] = f0[2]; f1[1] = f1[2];
            f0[2] = f0[3]; f1[2] = f1[3];
            {
                const ulonglong2* kr = kb + (size_t)rc * 16;
                f0[3] = kr[ln8];
                f1[3] = kr[8 + ln8];
            }
            p3 = red8(p3); p2 = red8(p2); p1 = red8(p1); p0 = red8(p0);
            if (ln8 == 0) {
                float bias = s_pb[d];
                s_wc[ql0 + 3][d] = (n3     >= d) ? fmaf(p3, sc, bias) : -1e30f;
                s_wc[ql0 + 2][d] = (n0 + 2 >= d) ? fmaf(p2, sc, bias) : -1e30f;
                s_wc[ql0 + 1][d] = (n0 + 1 >= d) ? fmaf(p1, sc, bias) : -1e30f;
                s_wc[ql0    ][d] = (n0     >= d) ? fmaf(p0, sc, bias) : -1e30f;
            }
        }

        // ---- sparse scores ----
        #pragma unroll
        for (int i = 0; i < NSPARSE; i++) {
            const int d  = c_soff[i];
            const int io = NDENSE + i;
            ulonglong2 e0 = s_se[io * 16 + ln8];
            ulonglong2 e1 = s_se[io * 16 + 8 + ln8];
            float ps_[QT];
            #pragma unroll
            for (int t = 0; t < QT; t++) {
                int r  = n0 + t - d;
                int rc = r < 0 ? 0 : r;
                const ulonglong2* kr = kb + (size_t)rc * 16;
                ps_[t] = dot8p(qa[t], qbr[t], u2add(kr[ln8], e0), u2add(kr[8 + ln8], e1));
            }
            #pragma unroll
            for (int t = 0; t < QT; t++) ps_[t] = red8(ps_[t]);
            if (ln8 == 0) {
                float bias = s_pb[io];
                #pragma unroll
                for (int t = 0; t < QT; t++)
                    s_wc[ql0 + t][io] = (n0 + t >= d) ? fmaf(ps_[t], sc, bias) : -1e30f;
            }
        }
    }
    __syncwarp();

    // ---- softmax: 2 lanes per query, 22 offsets each; write (w*cos, w*sin) ----
    {
        const int qloc = wid * QPW + (lane & 15);
        const int half = lane >> 4;
        const int base = half * 22;
        float vals[22];
        float vmax = -FLT_MAX;
        #pragma unroll
        for (int t = 0; t < 22; t++) {
            vals[t] = s_wc[qloc][base + t];
            vmax = fmaxf(vmax, vals[t]);
        }
        vmax = fmaxf(vmax, __shfl_xor_sync(0xffffffffu, vmax, 16));
        float sum = 0.f;
        #pragma unroll
        for (int t = 0; t < 22; t++) {
            vals[t] = __expf(vals[t] - vmax);
            sum += vals[t];
        }
        sum += __shfl_xor_sync(0xffffffffu, sum, 16);
        const float inv = 1.0f / sum;
        #pragma unroll
        for (int t = 0; t < 22; t++) {
            const int d = base + t;
            float w = vals[t] * inv;
            s_wc[qloc][d] = w * s_cos[d];
            s_ws[qloc][d] = w * s_sin[d];
        }
    }
    __syncthreads();

    // ---- cooperative vectorized store of weights to scratch ----
    {
        float2* gw = g_w + (bh + (size_t)nB) * NOFF;
        for (int idx = threadIdx.x; idx < QPB * NOFF; idx += TPB) {
            int nl = idx / NOFF;
            int d  = idx - nl * NOFF;
            gw[idx] = make_float2(s_wc[nl][d], s_ws[nl][d]);
        }
    }
}

// =====================================================================
// Kernel B: weighted rotated-V accumulation (A/B trick, rotate at end)
// =====================================================================
__global__ __launch_bounds__(TPB, 4)
void dsqg_value_kernel(const float* __restrict__ v,
                       float* __restrict__ out) {
    const int lane = threadIdx.x & 31;
    const int wid  = threadIdx.x >> 5;
    const int o    = lane >> 3;
    const int ln8  = lane & 7;

    __shared__ float2 s_w[QPB][SPAD];   // (w*cos, w*sin), padded rows

    const int h = blockIdx.y;
    const int b = blockIdx.z;
    const size_t bh = ((size_t)b * HNUM + h) * SEQ;
    const ulonglong2* vb = (const ulonglong2*)(v + bh * HD);

    const int ql0 = wid * QPW + o * QT;
    const int nB  = blockIdx.x * QPB;
    const int n0  = nB + ql0;
    const int n3  = n0 + 3;

    // ---- stage weights from scratch into smem (vectorized) ----
    {
        const float4* gsrc = (const float4*)(g_w + (bh + (size_t)nB) * NOFF);
        for (int idx = threadIdx.x; idx < QPB * NOFF / 2; idx += TPB) {
            float4 w2 = gsrc[idx];
            int e0 = idx * 2;
            int e1 = e0 + 1;
            int n0l = e0 / NOFF, d0 = e0 - n0l * NOFF;
            int n1l = e1 / NOFF, d1 = e1 - n1l * NOFF;
            s_w[n0l][d0] = make_float2(w2.x, w2.y);
            s_w[n1l][d1] = make_float2(w2.z, w2.w);
        }
    }
    __syncthreads();

    ulonglong2 A0[QT], A1[QT], B0[QT], B1[QT];
    #pragma unroll
    for (int t = 0; t < QT; t++) {
        A0[t].x = A0[t].y = A1[t].x = A1[t].y = 0ull;
        B0[t].x = B0[t].y = B1[t].x = B1[t].y = 0ull;
    }

    // ---- dense (4-deep FIFO; masked offsets have w == 0) ----
    {
        ulonglong2 f0[4], f1[4];
        #pragma unroll
        for (int j = 0; j < 4; j++) {
            const ulonglong2* vr = vb + (size_t)(n3 - j) * 16;
            f0[j] = vr[ln8];
            f1[j] = vr[8 + ln8];
        }
        #pragma unroll 3
        for (int d = 0; d < NDENSE; d++) {
            #pragma unroll
            for (int t = 0; t < QT; t++) {
                float2 w = s_w[ql0 + t][d];
                ull pcp = f2pack(w.x, w.x);
                ull psp = f2pack(w.y, w.y);
                A0[t].x = f2fma(f0[3 - t].x, pcp, A0[t].x);
                A0[t].y = f2fma(f0[3 - t].y, pcp, A0[t].y);
                A1[t].x = f2fma(f1[3 - t].x, pcp, A1[t].x);
                A1[t].y = f2fma(f1[3 - t].y, pcp, A1[t].y);
                B0[t].x = f2fma(f0[3 - t].x, psp, B0[t].x);
                B0[t].y = f2fma(f0[3 - t].y, psp, B0[t].y);
                B1[t].x = f2fma(f1[3 - t].x, psp, B1[t].x);
                B1[t].y = f2fma(f1[3 - t].y, psp, B1[t].y);
            }
            int rn = n0 - d - 1;
            int rc = rn < 0 ? 0 : rn;
            f0[0] = f0[1]; f1[0] = f1[1];
            f0[1] = f0[2]; f1[1] = f1[2];
            f0[2] = f0[3]; f1[2] = f1[3];
            {
                const ulonglong2* vr = vb + (size_t)rc * 16;
                f0[3] = vr[ln8];
                f1[3] = vr[8 + ln8];
            }
        }
    }

    // ---- sparse (w == 0 self-masks) ----
    #pragma unroll
    for (int i = 0; i < NSPARSE; i++) {
        const int d  = c_soff[i];
        const int io = NDENSE + i;
        #pragma unroll
        for (int t = 0; t < QT; t++) {
            int r  = n0 + t - d;
            int rc = r < 0 ? 0 : r;
            float2 w = s_w[ql0 + t][io];
            ull pcp = f2pack(w.x, w.x);
            ull psp = f2pack(w.y, w.y);
            const ulonglong2* vr = vb + (size_t)rc * 16;
            ulonglong2 v0 = vr[ln8];
            ulonglong2 v1 = vr[8 + ln8];
            A0[t].x = f2fma(v0.x, pcp, A0[t].x);
            A0[t].y = f2fma(v0.y, pcp, A0[t].y);
            A1[t].x = f2fma(v1.x, pcp, A1[t].x);
            A1[t].y = f2fma(v1.y, pcp, A1[t].y);
            B0[t].x = f2fma(v0.x, psp, B0[t].x);
            B0[t].y = f2fma(v0.y, psp, B0[t].y);
            B1[t].x = f2fma(v1.x, psp, B1[t].x);
            B1[t].y = f2fma(v1.y, psp, B1[t].y);
        }
    }

    // ---- final rotation + store ----
    #pragma unroll
    for (int t = 0; t < QT; t++) {
        float4* op = (float4*)(out + (bh + (size_t)(n0 + t)) * HD);
        float2 a0 = f2unpack(A0[t].x), b0 = f2unpack(B0[t].x);
        float2 a1 = f2unpack(A0[t].y), b1 = f2unpack(B0[t].y);
        float2 a2 = f2unpack(A1[t].x), b2 = f2unpack(B1[t].x);
        float2 a3 = f2unpack(A1[t].y), b3 = f2unpack(B1[t].y);
        float4 r0, r1;
        r0.x = a0.x - b0.y;  r0.y = a0.y + b0.x;
        r0.z = a1.x - b1.y;  r0.w = a1.y + b1.x;
        r1.x = a2.x - b2.y;  r1.y = a2.y + b2.x;
        r1.z = a3.x - b3.y;  r1.w = a3.y + b3.x;
        op[ln8]     = r0;
        op[8 + ln8] = r1;
    }
}

extern "C" void kernel_launch(void* const* d_in, const int* in_sizes, int n_in,
                              void* d_out, int out_size) {
    const float* q  = (const float*)d_in[0];
    const float* k  = (const float*)d_in[1];
    const float* v  = (const float*)d_in[2];
    const float* pb = (const float*)d_in[3];
    const float* se = (const float*)d_in[4];
    const float* ph = (const float*)d_in[5];
    float* out = (float*)d_out;

    dim3 grid(SEQ / QPB, HNUM, BNUM);
    dsqg_scores_kernel<<<grid, TPB>>>(q, k, pb, se, ph);
    dsqg_value_kernel<<<grid, TPB>>>(v, out);
}